// round 2
// baseline (speedup 1.0000x reference)
#include <cuda_runtime.h>
#include <math.h>

#define NROWS 32
#define NCOLS 512
#define NPAIRS 130816            // 512*511/2
#define CHUNKS 16
#define PAIRS_PER_CHUNK (NPAIRS / CHUNKS)   // 8176
#define TSTW 512                 // tau / w table size, domain [0,1]
#define TSG 4096                 // g table size
#define G_MIN (-24.0f)
#define G_RANGE 64.0f            // g domain [-24, 40]
#define NB_TAU 8
#define NB_G 8
#define NB_W 6
#define W_FLOOR 0.001f

// ---------------- device scratch (no allocations allowed) ----------------
__device__ float  d_s[NROWS * NCOLS];          // normalized scores
__device__ float2 d_tab_tau[TSTW];             // (value, delta) lerp tables
__device__ float2 d_tab_w[TSTW];
__device__ float2 d_tab_g[TSG];
__device__ double d_row_sum[NROWS];
__device__ unsigned long long d_row_cnt[NROWS];

__device__ __forceinline__ float softplusf(float z) {
    // stable: max(z,0) + log1p(exp(-|z|))
    return fmaxf(z, 0.0f) + log1pf(expf(-fabsf(z)));
}
__device__ __forceinline__ float sigmoidf(float z) {
    return 1.0f / (1.0f + expf(-z));
}

__device__ __forceinline__ float eval_sp(float x, const float* __restrict__ th, int nb) {
    float acc = 0.0f;
    for (int i = 0; i < nb; i++) {
        float sl = 0.5f + 3.5f * (float)i / (float)(nb - 1);
        float bi = -2.0f + 4.0f * (float)i / (float)(nb - 1);
        acc += softplusf(th[i]) * softplusf(fmaf(x, sl, bi));
    }
    return acc;
}
__device__ __forceinline__ float eval_sg(float x, const float* __restrict__ th, int nb) {
    float acc = 0.0f;
    for (int i = 0; i < nb; i++) {
        float sl = 0.5f + 3.5f * (float)i / (float)(nb - 1);
        float bi = -2.0f + 4.0f * (float)i / (float)(nb - 1);
        acc += softplusf(th[i]) * sigmoidf(fmaf(x, sl, bi));
    }
    return acc;
}

// ---------------- kernel A: normalization + tables + zeroing (fused) ---------
// block 0   : per-row masked mean/var normalization (32 warps, 1 per row) + zero accumulators
// blocks 1-5: build lerp tables (1024 entries each), recomputing coefficients locally
__global__ void __launch_bounds__(1024) setup_kernel(
    const float* __restrict__ pred, const float* __restrict__ tg,
    const float* __restrict__ th_tau, const float* __restrict__ th_g,
    const float* __restrict__ th_w)
{
    int tid = threadIdx.x;
    if (blockIdx.x == 0) {
        // zero accumulators (graph replays -> must re-zero every launch)
        if (tid < NROWS) {
            d_row_sum[tid] = 0.0;
            d_row_cnt[tid] = 0ull;
        }
        // one warp per row: masked mean/var normalization
        int w = tid >> 5, lane = tid & 31;
        const float* p = pred + w * NCOLS;
        const float* t = tg   + w * NCOLS;
        float lp[16]; bool lm[16];
        float sum = 0.0f; int cnt = 0;
#pragma unroll
        for (int u = 0; u < 16; u++) {
            float tv = t[lane + 32 * u];
            bool  m  = fabsf(tv + 1.0f) > 1.00001e-5f;   // ~jnp.isclose(t,-1) negated
            float pv = p[lane + 32 * u];
            lp[u] = pv; lm[u] = m;
            sum += m ? pv : 0.0f;
            cnt += m ? 1 : 0;
        }
#pragma unroll
        for (int o = 16; o; o >>= 1) {
            sum += __shfl_xor_sync(0xffffffffu, sum, o);
            cnt += __shfl_xor_sync(0xffffffffu, cnt, o);
        }
        float denom = fmaxf((float)cnt, 1.0f);
        float mean  = sum / denom;
        float var = 0.0f;
#pragma unroll
        for (int u = 0; u < 16; u++) {
            float dd = lp[u] - mean;
            var += lm[u] ? dd * dd : 0.0f;
        }
#pragma unroll
        for (int o = 16; o; o >>= 1) var += __shfl_xor_sync(0xffffffffu, var, o);
        var /= denom;
        float inv = rsqrtf(var + 1e-6f);
#pragma unroll
        for (int u = 0; u < 16; u++)
            d_s[w * NCOLS + lane + 32 * u] = (lp[u] - mean) * inv;
    } else {
        int e = (blockIdx.x - 1) * 1024 + tid;    // 0 .. 5119
        if (e < TSTW) {
            float h = 1.0f / (float)(TSTW - 1);
            float x = (float)e * h;
            float v0 = eval_sp(x,     th_tau, NB_TAU);
            float v1 = eval_sp(x + h, th_tau, NB_TAU);
            d_tab_tau[e] = make_float2(v0, v1 - v0);
        } else if (e < 2 * TSTW) {
            int i = e - TSTW;
            float h = 1.0f / (float)(TSTW - 1);
            float x = (float)i * h;
            float v0 = eval_sg(x,     th_w, NB_W);
            float v1 = eval_sg(x + h, th_w, NB_W);
            d_tab_w[i] = make_float2(v0, v1 - v0);
        } else if (e < 2 * TSTW + TSG) {
            int i = e - 2 * TSTW;
            float h = G_RANGE / (float)(TSG - 1);
            float x = G_MIN + (float)i * h;
            float v0 = eval_sp(x,     th_g, NB_G);
            float v1 = eval_sp(x + h, th_g, NB_G);
            d_tab_g[i] = make_float2(v0, v1 - v0);
        }
    }
}

// ---------------- kernel B: pair loop ----------------
__global__ void __launch_bounds__(256) pair_kernel(const float* __restrict__ tg) {
    __shared__ float2 sh_g[TSG];       // 32 KB
    __shared__ float2 sh_tau[TSTW];    // 4 KB
    __shared__ float2 sh_w[TSTW];      // 4 KB
    __shared__ float2 sh_rs[NCOLS];    // 4 KB  (r or NaN-if-masked, s)
    __shared__ float  red_s[8];
    __shared__ int    red_c[8];

    int tid = threadIdx.x;
    int b   = blockIdx.y;

    // load row data; encode invalid entries as NaN in r (pairs auto-dropped)
    for (int idx = tid; idx < NCOLS; idx += 256) {
        float rv = tg[b * NCOLS + idx];
        bool  m  = fabsf(rv + 1.0f) > 1.00001e-5f;
        float sv = d_s[b * NCOLS + idx];
        sh_rs[idx] = make_float2(m ? rv : __int_as_float(0x7fffffff), sv);
    }
    // bulk-copy tables (float4)
    {
        const float4* sg = (const float4*)d_tab_g;   float4* dg = (float4*)sh_g;
        for (int idx = tid; idx < TSG / 2; idx += 256) dg[idx] = sg[idx];
        const float4* st = (const float4*)d_tab_tau; float4* dt = (float4*)sh_tau;
        const float4* sw = (const float4*)d_tab_w;   float4* dw = (float4*)sh_w;
        for (int idx = tid; idx < TSTW / 2; idx += 256) { dt[idx] = st[idx]; dw[idx] = sw[idx]; }
    }
    __syncthreads();

    const float inv_hg = (float)(TSG - 1) / G_RANGE;
    int start = blockIdx.x * PAIRS_PER_CHUNK;
    int end   = start + PAIRS_PER_CHUNK;

    float acc = 0.0f; int cnt = 0;
    for (int k = start + tid; k < end; k += 256) {
        // balanced triangular decode: rows v and 510-v folded to length 512
        int v   = k >> 9;
        int off = k & 511;
        int lim = 511 - v;
        int i = (off < lim) ? v           : 510 - v;
        int j = (off < lim) ? v + 1 + off : off;

        float2 pi = sh_rs[i];   // broadcast across warp
        float2 pj = sh_rs[j];   // consecutive, conflict-free
        float dr = pi.x - pj.x;
        float ds = pi.y - pj.y;
        bool pos = dr > 0.0f, neg = dr < 0.0f;
        if (pos | neg) {                        // drops ties and NaN (masked)
            float adr = fabsf(dr);
            float tds = pos ? ds : -ds;         // t * ds

            float pt = fminf(adr, 1.0f) * (float)(TSTW - 1);
            int   it = min((int)pt, TSTW - 2);
            float ft = pt - (float)it;
            float2 et = sh_tau[it];
            float tau = fmaf(ft, et.y, et.x);

            float m  = tau - tds;
            float pg = fmaxf((m - G_MIN) * inv_hg, 0.0f);
            int   ig = min((int)pg, TSG - 2);
            float fg = pg - (float)ig;          // frac>1 at top = exact linear ext
            float2 eg = sh_g[ig];
            float g  = fmaf(fg, eg.y, eg.x);

            float2 ew = sh_w[it];               // same index as tau
            float w  = W_FLOOR + fmaf(ft, ew.y, ew.x);

            acc += g * w;
            cnt += 1;
        }
    }

#pragma unroll
    for (int o = 16; o; o >>= 1) {
        acc += __shfl_xor_sync(0xffffffffu, acc, o);
        cnt += __shfl_xor_sync(0xffffffffu, cnt, o);
    }
    if ((tid & 31) == 0) { red_s[tid >> 5] = acc; red_c[tid >> 5] = cnt; }
    __syncthreads();
    if (tid == 0) {
        float bs = 0.0f; int bc = 0;
#pragma unroll
        for (int u = 0; u < 8; u++) { bs += red_s[u]; bc += red_c[u]; }
        atomicAdd(&d_row_sum[b], (double)bs);
        atomicAdd(&d_row_cnt[b], (unsigned long long)bc);
    }
}

// ---------------- kernel C: finalize ----------------
__global__ void final_kernel(float* __restrict__ out) {
    int lane = threadIdx.x;   // 32 threads, one per row
    double s = d_row_sum[lane];
    unsigned long long c = d_row_cnt[lane];
    float denom = fmaxf((float)c, 1.0f);
    float rl    = (float)(s / (double)denom);
    float valid = (c > 0ull) ? 1.0f : 0.0f;
    float num   = rl * valid;
#pragma unroll
    for (int o = 16; o; o >>= 1) {
        num   += __shfl_xor_sync(0xffffffffu, num, o);
        valid += __shfl_xor_sync(0xffffffffu, valid, o);
    }
    if (lane == 0) out[0] = num / fmaxf(valid, 1.0f);
}

// ---------------- launch ----------------
extern "C" void kernel_launch(void* const* d_in, const int* in_sizes, int n_in,
                              void* d_out, int out_size) {
    const float* pred   = (const float*)d_in[0];
    const float* tg     = (const float*)d_in[1];
    const float* th_tau = (const float*)d_in[2];
    const float* th_g   = (const float*)d_in[3];
    const float* th_w   = (const float*)d_in[4];

    setup_kernel<<<6, 1024>>>(pred, tg, th_tau, th_g, th_w);
    dim3 grid(CHUNKS, NROWS);
    pair_kernel<<<grid, 256>>>(tg);
    final_kernel<<<1, 32>>>((float*)d_out);
}

// round 3
// speedup vs baseline: 1.0021x; 1.0021x over previous
#include <cuda_runtime.h>
#include <math.h>

#define NROWS 32
#define NCOLS 512
#define NPAIRS 130816            // 512*511/2
#define CHUNKS 16
#define PAIRS_PER_CHUNK (NPAIRS / CHUNKS)   // 8176
#define TSTW 512                 // tau / w table size, domain [0,1]
#define TSG 4096                 // g table size
#define G_MIN (-24.0f)
#define G_RANGE 64.0f            // g domain [-24, 40]
#define NB_TAU 8
#define NB_G 8
#define NB_W 6
#define W_FLOOR 0.001f

// ---------------- device scratch (no allocations allowed) ----------------
__device__ float  d_s[NROWS * NCOLS];          // normalized scores
__device__ float2 d_tab_tau[TSTW];             // (value, delta) lerp tables
__device__ float2 d_tab_w[TSTW];
__device__ float2 d_tab_g[TSG];
__device__ double d_row_sum[NROWS];
__device__ unsigned long long d_row_cnt[NROWS];

__device__ __forceinline__ float softplusf(float z) {
    // stable: max(z,0) + log1p(exp(-|z|))
    return fmaxf(z, 0.0f) + log1pf(expf(-fabsf(z)));
}
__device__ __forceinline__ float sigmoidf(float z) {
    return 1.0f / (1.0f + expf(-z));
}

__device__ __forceinline__ float eval_sp(float x, const float* __restrict__ th, int nb) {
    float acc = 0.0f;
    for (int i = 0; i < nb; i++) {
        float sl = 0.5f + 3.5f * (float)i / (float)(nb - 1);
        float bi = -2.0f + 4.0f * (float)i / (float)(nb - 1);
        acc += softplusf(th[i]) * softplusf(fmaf(x, sl, bi));
    }
    return acc;
}
__device__ __forceinline__ float eval_sg(float x, const float* __restrict__ th, int nb) {
    float acc = 0.0f;
    for (int i = 0; i < nb; i++) {
        float sl = 0.5f + 3.5f * (float)i / (float)(nb - 1);
        float bi = -2.0f + 4.0f * (float)i / (float)(nb - 1);
        acc += softplusf(th[i]) * sigmoidf(fmaf(x, sl, bi));
    }
    return acc;
}

// ---------------- kernel A: normalization + tables + zeroing (fused) ---------
// block 0   : per-row masked mean/var normalization (32 warps, 1 per row) + zero accumulators
// blocks 1-5: build lerp tables (1024 entries each), recomputing coefficients locally
__global__ void __launch_bounds__(1024) setup_kernel(
    const float* __restrict__ pred, const float* __restrict__ tg,
    const float* __restrict__ th_tau, const float* __restrict__ th_g,
    const float* __restrict__ th_w)
{
    int tid = threadIdx.x;
    if (blockIdx.x == 0) {
        // zero accumulators (graph replays -> must re-zero every launch)
        if (tid < NROWS) {
            d_row_sum[tid] = 0.0;
            d_row_cnt[tid] = 0ull;
        }
        // one warp per row: masked mean/var normalization
        int w = tid >> 5, lane = tid & 31;
        const float* p = pred + w * NCOLS;
        const float* t = tg   + w * NCOLS;
        float lp[16]; bool lm[16];
        float sum = 0.0f; int cnt = 0;
#pragma unroll
        for (int u = 0; u < 16; u++) {
            float tv = t[lane + 32 * u];
            bool  m  = fabsf(tv + 1.0f) > 1.00001e-5f;   // ~jnp.isclose(t,-1) negated
            float pv = p[lane + 32 * u];
            lp[u] = pv; lm[u] = m;
            sum += m ? pv : 0.0f;
            cnt += m ? 1 : 0;
        }
#pragma unroll
        for (int o = 16; o; o >>= 1) {
            sum += __shfl_xor_sync(0xffffffffu, sum, o);
            cnt += __shfl_xor_sync(0xffffffffu, cnt, o);
        }
        float denom = fmaxf((float)cnt, 1.0f);
        float mean  = sum / denom;
        float var = 0.0f;
#pragma unroll
        for (int u = 0; u < 16; u++) {
            float dd = lp[u] - mean;
            var += lm[u] ? dd * dd : 0.0f;
        }
#pragma unroll
        for (int o = 16; o; o >>= 1) var += __shfl_xor_sync(0xffffffffu, var, o);
        var /= denom;
        float inv = rsqrtf(var + 1e-6f);
#pragma unroll
        for (int u = 0; u < 16; u++)
            d_s[w * NCOLS + lane + 32 * u] = (lp[u] - mean) * inv;
    } else {
        int e = (blockIdx.x - 1) * 1024 + tid;    // 0 .. 5119
        if (e < TSTW) {
            float h = 1.0f / (float)(TSTW - 1);
            float x = (float)e * h;
            float v0 = eval_sp(x,     th_tau, NB_TAU);
            float v1 = eval_sp(x + h, th_tau, NB_TAU);
            d_tab_tau[e] = make_float2(v0, v1 - v0);
        } else if (e < 2 * TSTW) {
            int i = e - TSTW;
            float h = 1.0f / (float)(TSTW - 1);
            float x = (float)i * h;
            float v0 = eval_sg(x,     th_w, NB_W);
            float v1 = eval_sg(x + h, th_w, NB_W);
            d_tab_w[i] = make_float2(v0, v1 - v0);
        } else if (e < 2 * TSTW + TSG) {
            int i = e - 2 * TSTW;
            float h = G_RANGE / (float)(TSG - 1);
            float x = G_MIN + (float)i * h;
            float v0 = eval_sp(x,     th_g, NB_G);
            float v1 = eval_sp(x + h, th_g, NB_G);
            d_tab_g[i] = make_float2(v0, v1 - v0);
        }
    }
}

// ---------------- kernel B: pair loop ----------------
__global__ void __launch_bounds__(256) pair_kernel(const float* __restrict__ tg) {
    __shared__ float2 sh_g[TSG];       // 32 KB
    __shared__ float2 sh_tau[TSTW];    // 4 KB
    __shared__ float2 sh_w[TSTW];      // 4 KB
    __shared__ float2 sh_rs[NCOLS];    // 4 KB  (r or NaN-if-masked, s)
    __shared__ float  red_s[8];
    __shared__ int    red_c[8];

    int tid = threadIdx.x;
    int b   = blockIdx.y;

    // load row data; encode invalid entries as NaN in r (pairs auto-dropped)
    for (int idx = tid; idx < NCOLS; idx += 256) {
        float rv = tg[b * NCOLS + idx];
        bool  m  = fabsf(rv + 1.0f) > 1.00001e-5f;
        float sv = d_s[b * NCOLS + idx];
        sh_rs[idx] = make_float2(m ? rv : __int_as_float(0x7fffffff), sv);
    }
    // bulk-copy tables (float4)
    {
        const float4* sg = (const float4*)d_tab_g;   float4* dg = (float4*)sh_g;
        for (int idx = tid; idx < TSG / 2; idx += 256) dg[idx] = sg[idx];
        const float4* st = (const float4*)d_tab_tau; float4* dt = (float4*)sh_tau;
        const float4* sw = (const float4*)d_tab_w;   float4* dw = (float4*)sh_w;
        for (int idx = tid; idx < TSTW / 2; idx += 256) { dt[idx] = st[idx]; dw[idx] = sw[idx]; }
    }
    __syncthreads();

    const float inv_hg = (float)(TSG - 1) / G_RANGE;
    int start = blockIdx.x * PAIRS_PER_CHUNK;
    int end   = start + PAIRS_PER_CHUNK;

    float acc = 0.0f; int cnt = 0;
    for (int k = start + tid; k < end; k += 256) {
        // balanced triangular decode: rows v and 510-v folded to length 512
        int v   = k >> 9;
        int off = k & 511;
        int lim = 511 - v;
        int i = (off < lim) ? v           : 510 - v;
        int j = (off < lim) ? v + 1 + off : off;

        float2 pi = sh_rs[i];   // broadcast across warp
        float2 pj = sh_rs[j];   // consecutive, conflict-free
        float dr = pi.x - pj.x;
        float ds = pi.y - pj.y;
        bool pos = dr > 0.0f, neg = dr < 0.0f;
        if (pos | neg) {                        // drops ties and NaN (masked)
            float adr = fabsf(dr);
            float tds = pos ? ds : -ds;         // t * ds

            float pt = fminf(adr, 1.0f) * (float)(TSTW - 1);
            int   it = min((int)pt, TSTW - 2);
            float ft = pt - (float)it;
            float2 et = sh_tau[it];
            float tau = fmaf(ft, et.y, et.x);

            float m  = tau - tds;
            float pg = fmaxf((m - G_MIN) * inv_hg, 0.0f);
            int   ig = min((int)pg, TSG - 2);
            float fg = pg - (float)ig;          // frac>1 at top = exact linear ext
            float2 eg = sh_g[ig];
            float g  = fmaf(fg, eg.y, eg.x);

            float2 ew = sh_w[it];               // same index as tau
            float w  = W_FLOOR + fmaf(ft, ew.y, ew.x);

            acc += g * w;
            cnt += 1;
        }
    }

#pragma unroll
    for (int o = 16; o; o >>= 1) {
        acc += __shfl_xor_sync(0xffffffffu, acc, o);
        cnt += __shfl_xor_sync(0xffffffffu, cnt, o);
    }
    if ((tid & 31) == 0) { red_s[tid >> 5] = acc; red_c[tid >> 5] = cnt; }
    __syncthreads();
    if (tid == 0) {
        float bs = 0.0f; int bc = 0;
#pragma unroll
        for (int u = 0; u < 8; u++) { bs += red_s[u]; bc += red_c[u]; }
        atomicAdd(&d_row_sum[b], (double)bs);
        atomicAdd(&d_row_cnt[b], (unsigned long long)bc);
    }
}

// ---------------- kernel C: finalize ----------------
__global__ void final_kernel(float* __restrict__ out) {
    int lane = threadIdx.x;   // 32 threads, one per row
    double s = d_row_sum[lane];
    unsigned long long c = d_row_cnt[lane];
    float denom = fmaxf((float)c, 1.0f);
    float rl    = (float)(s / (double)denom);
    float valid = (c > 0ull) ? 1.0f : 0.0f;
    float num   = rl * valid;
#pragma unroll
    for (int o = 16; o; o >>= 1) {
        num   += __shfl_xor_sync(0xffffffffu, num, o);
        valid += __shfl_xor_sync(0xffffffffu, valid, o);
    }
    if (lane == 0) out[0] = num / fmaxf(valid, 1.0f);
}

// ---------------- launch ----------------
extern "C" void kernel_launch(void* const* d_in, const int* in_sizes, int n_in,
                              void* d_out, int out_size) {
    const float* pred   = (const float*)d_in[0];
    const float* tg     = (const float*)d_in[1];
    const float* th_tau = (const float*)d_in[2];
    const float* th_g   = (const float*)d_in[3];
    const float* th_w   = (const float*)d_in[4];

    setup_kernel<<<6, 1024>>>(pred, tg, th_tau, th_g, th_w);
    dim3 grid(CHUNKS, NROWS);
    pair_kernel<<<grid, 256>>>(tg);
    final_kernel<<<1, 32>>>((float*)d_out);
}

// round 4
// speedup vs baseline: 1.4863x; 1.4832x over previous
#include <cuda_runtime.h>
#include <math.h>

#define NROWS 32
#define NCOLS 512
#define NPAIRS 130816            // 512*511/2
#define CHUNKS 16
#define PAIRS_PER_CHUNK (NPAIRS / CHUNKS)   // 8176 (exact)
#define TSTW 512                 // tau / w merged table size, domain [0,1]
#define TSG 2048                 // g table size
#define G_MIN (-24.0f)
#define G_RANGE 64.0f            // g domain [-24, 40]
#define NB_TAU 8
#define NB_G 8
#define NB_W 6
#define W_FLOOR 0.001f

// ---------------- device scratch (no allocations allowed) ----------------
__device__ float4 d_tab_tw[TSTW];              // (tau0, dtau, w0, dw)
__device__ float2 d_tab_g[TSG];                // (g0, dg)
__device__ float  d_part_sum[NROWS * CHUNKS];  // per-block partials (always written)
__device__ int    d_part_cnt[NROWS * CHUNKS];

// fast-math activations (table build only; table err budget is huge: rel_err was 3e-7)
__device__ __forceinline__ float fsp(float z) {
    return fmaxf(z, 0.0f) + __logf(1.0f + __expf(-fabsf(z)));
}
__device__ __forceinline__ float fsg(float z) {
    return __fdividef(1.0f, 1.0f + __expf(-z));
}

// ---------------- kernel A: build lerp tables (fast-math, 20 blocks) --------
__global__ void __launch_bounds__(128) table_kernel(
    const float* __restrict__ th_tau, const float* __restrict__ th_g,
    const float* __restrict__ th_w)
{
    int e = blockIdx.x * 128 + threadIdx.x;   // 0 .. TSTW+TSG-1 (= 2559)
    if (e < TSTW) {
        float ct[NB_TAU], cw[NB_W];
#pragma unroll
        for (int i = 0; i < NB_TAU; i++) ct[i] = fsp(th_tau[i]);
#pragma unroll
        for (int i = 0; i < NB_W; i++)   cw[i] = fsp(th_w[i]);
        float h = 1.0f / (float)(TSTW - 1);
        float x = (float)e * h;
        float t0 = 0.f, t1 = 0.f, w0 = 0.f, w1 = 0.f;
#pragma unroll
        for (int i = 0; i < NB_TAU; i++) {
            float sl = 0.5f + 3.5f * (float)i / (float)(NB_TAU - 1);
            float bi = -2.0f + 4.0f * (float)i / (float)(NB_TAU - 1);
            t0 += ct[i] * fsp(fmaf(x,     sl, bi));
            t1 += ct[i] * fsp(fmaf(x + h, sl, bi));
        }
#pragma unroll
        for (int i = 0; i < NB_W; i++) {
            float sl = 0.5f + 3.5f * (float)i / (float)(NB_W - 1);
            float bi = -2.0f + 4.0f * (float)i / (float)(NB_W - 1);
            w0 += cw[i] * fsg(fmaf(x,     sl, bi));
            w1 += cw[i] * fsg(fmaf(x + h, sl, bi));
        }
        d_tab_tw[e] = make_float4(t0, t1 - t0, w0, w1 - w0);
    } else if (e < TSTW + TSG) {
        int i = e - TSTW;
        float cg[NB_G];
#pragma unroll
        for (int u = 0; u < NB_G; u++) cg[u] = fsp(th_g[u]);
        float h = G_RANGE / (float)(TSG - 1);
        float x = G_MIN + (float)i * h;
        float v0 = 0.f, v1 = 0.f;
#pragma unroll
        for (int u = 0; u < NB_G; u++) {
            float sl = 0.5f + 3.5f * (float)u / (float)(NB_G - 1);
            float bi = -2.0f + 4.0f * (float)u / (float)(NB_G - 1);
            v0 += cg[u] * fsp(fmaf(x,     sl, bi));
            v1 += cg[u] * fsp(fmaf(x + h, sl, bi));
        }
        d_tab_g[i] = make_float2(v0, v1 - v0);
    }
}

// ---------------- kernel B: normalization + pair loop (fused) ----------------
__global__ void __launch_bounds__(256) pair_kernel(
    const float* __restrict__ pred, const float* __restrict__ tg)
{
    __shared__ float2 sh_g[TSG];       // 16 KB
    __shared__ float4 sh_tw[TSTW];     // 8 KB
    __shared__ float2 sh_rs[NCOLS];    // 4 KB  (r or NaN-if-masked, s)
    __shared__ float  red_f[8];
    __shared__ float  red_f2[8];
    __shared__ int    red_i[8];
    __shared__ float  bcast[2];

    int tid  = threadIdx.x;
    int b    = blockIdx.y;
    int lane = tid & 31, warp = tid >> 5;

    // ---- load this row (2 elems/thread) ----
    const float* tr = tg   + b * NCOLS;
    const float* pr = pred + b * NCOLS;
    float t0 = tr[tid], t1 = tr[tid + 256];
    float p0 = pr[tid], p1 = pr[tid + 256];
    bool  m0 = fabsf(t0 + 1.0f) > 1.00001e-5f;   // ~jnp.isclose(t,-1) negated
    bool  m1 = fabsf(t1 + 1.0f) > 1.00001e-5f;

    // ---- table copy gmem -> smem (overlaps with reduction) ----
    {
        const float4* sg = (const float4*)d_tab_g;   float4* dg = (float4*)sh_g;
#pragma unroll
        for (int u = 0; u < TSG / 2 / 256; u++) dg[tid + 256 * u] = sg[tid + 256 * u];
        sh_tw[tid]       = d_tab_tw[tid];
        sh_tw[tid + 256] = d_tab_tw[tid + 256];
    }

    // ---- one-pass masked mean / var (block reduction) ----
    float sum = (m0 ? p0 : 0.f) + (m1 ? p1 : 0.f);
    float ssq = (m0 ? p0 * p0 : 0.f) + (m1 ? p1 * p1 : 0.f);
    int   cnt = (int)m0 + (int)m1;
#pragma unroll
    for (int o = 16; o; o >>= 1) {
        sum += __shfl_xor_sync(0xffffffffu, sum, o);
        ssq += __shfl_xor_sync(0xffffffffu, ssq, o);
        cnt += __shfl_xor_sync(0xffffffffu, cnt, o);
    }
    if (lane == 0) { red_f[warp] = sum; red_f2[warp] = ssq; red_i[warp] = cnt; }
    __syncthreads();
    if (tid == 0) {
        float s = 0.f, q = 0.f; int c = 0;
#pragma unroll
        for (int u = 0; u < 8; u++) { s += red_f[u]; q += red_f2[u]; c += red_i[u]; }
        float denom = fmaxf((float)c, 1.0f);
        float mean  = s / denom;
        float var   = q / denom - mean * mean;
        bcast[0] = mean;
        bcast[1] = rsqrtf(var + 1e-6f);
    }
    __syncthreads();
    float mean = bcast[0], inv = bcast[1];
    const float qnan = __int_as_float(0x7fffffff);
    sh_rs[tid]       = make_float2(m0 ? t0 : qnan, (p0 - mean) * inv);
    sh_rs[tid + 256] = make_float2(m1 ? t1 : qnan, (p1 - mean) * inv);
    __syncthreads();

    // ---- pair loop ----
    const float inv_hg = (float)(TSG - 1) / G_RANGE;
    int start = blockIdx.x * PAIRS_PER_CHUNK;
    int end   = start + PAIRS_PER_CHUNK;

    float acc = 0.0f; int pcnt = 0;
#pragma unroll 2
    for (int k = start + tid; k < end; k += 256) {
        // balanced triangular decode: rows v and 510-v folded to length 512
        int v   = k >> 9;
        int off = k & 511;
        int lim = 511 - v;
        int i = (off < lim) ? v           : 510 - v;
        int j = (off < lim) ? v + 1 + off : off;

        float2 pi = sh_rs[i];   // broadcast across warp (usually uniform v)
        float2 pj = sh_rs[j];   // consecutive, conflict-free
        float dr = pi.x - pj.x;
        float ds = pi.y - pj.y;
        bool pos = dr > 0.0f, neg = dr < 0.0f;
        if (pos | neg) {                        // drops ties and NaN (masked)
            float adr = fabsf(dr);
            float tds = pos ? ds : -ds;         // t * ds

            float pt = fminf(adr, 1.0f) * (float)(TSTW - 1);
            int   it = min((int)pt, TSTW - 2);
            float ft = pt - (float)it;
            float4 etw = sh_tw[it];             // one LDS.128: tau + w
            float tau = fmaf(ft, etw.y, etw.x);
            float w   = W_FLOOR + fmaf(ft, etw.w, etw.z);

            float m  = tau - tds;
            float pg = fmaxf((m - G_MIN) * inv_hg, 0.0f);
            int   ig = min((int)pg, TSG - 2);
            float fg = pg - (float)ig;          // frac>1 at top = exact linear ext
            float2 eg = sh_g[ig];
            float g  = fmaf(fg, eg.y, eg.x);

            acc += g * w;
            pcnt += 1;
        }
    }

#pragma unroll
    for (int o = 16; o; o >>= 1) {
        acc  += __shfl_xor_sync(0xffffffffu, acc, o);
        pcnt += __shfl_xor_sync(0xffffffffu, pcnt, o);
    }
    __syncthreads();   // red_f / red_i reuse
    if (lane == 0) { red_f[warp] = acc; red_i[warp] = pcnt; }
    __syncthreads();
    if (tid == 0) {
        float bs = 0.0f; int bc = 0;
#pragma unroll
        for (int u = 0; u < 8; u++) { bs += red_f[u]; bc += red_i[u]; }
        d_part_sum[b * CHUNKS + blockIdx.x] = bs;
        d_part_cnt[b * CHUNKS + blockIdx.x] = bc;
    }
}

// ---------------- kernel C: finalize ----------------
__global__ void __launch_bounds__(512) final_kernel(float* __restrict__ out) {
    __shared__ float s_num[32];
    __shared__ float s_val[32];
    int tid = threadIdx.x;             // 512 threads = 32 rows x 16 chunks
    float ps = d_part_sum[tid];
    int   pc = d_part_cnt[tid];
#pragma unroll
    for (int o = 8; o; o >>= 1) {      // reduce within 16-lane groups
        ps += __shfl_xor_sync(0xffffffffu, ps, o);
        pc += __shfl_xor_sync(0xffffffffu, pc, o);
    }
    if ((tid & 15) == 0) {
        int row = tid >> 4;
        float denom = fmaxf((float)pc, 1.0f);
        float rl    = ps / denom;
        float valid = (pc > 0) ? 1.0f : 0.0f;
        s_num[row] = rl * valid;
        s_val[row] = valid;
    }
    __syncthreads();
    if (tid < 32) {
        float n = s_num[tid], v = s_val[tid];
#pragma unroll
        for (int o = 16; o; o >>= 1) {
            n += __shfl_xor_sync(0xffffffffu, n, o);
            v += __shfl_xor_sync(0xffffffffu, v, o);
        }
        if (tid == 0) out[0] = n / fmaxf(v, 1.0f);
    }
}

// ---------------- launch ----------------
extern "C" void kernel_launch(void* const* d_in, const int* in_sizes, int n_in,
                              void* d_out, int out_size) {
    const float* pred   = (const float*)d_in[0];
    const float* tg     = (const float*)d_in[1];
    const float* th_tau = (const float*)d_in[2];
    const float* th_g   = (const float*)d_in[3];
    const float* th_w   = (const float*)d_in[4];

    table_kernel<<<(TSTW + TSG) / 128, 128>>>(th_tau, th_g, th_w);
    dim3 grid(CHUNKS, NROWS);
    pair_kernel<<<grid, 256>>>(pred, tg);
    final_kernel<<<1, 512>>>((float*)d_out);
}